// round 13
// baseline (speedup 1.0000x reference)
#include <cuda_runtime.h>

#define NAG    12
#define NENV   4096
#define NNODE  (NENV*NAG)
#define TPB    192

// shared float offsets
#define OFF_WA   0        // 4096 paired-k (half of We1 / Wh1)
#define OFF_WB   4096     // 4096 (We2 plain row-major ; Wemb/Wh2 paired)
#define OFF_H    8192     // 12x64
#define OFF_P2   8960     // P2 float2[12][32]
#define OFF_XS0  9728     // 144
#define OFF_XS1  9872     // 144
#define OFF_RAD  10016    // 132x4
#define OFF_MS   10544    // 6 warps x 384 (msw batch6; agg@+0..127, t1s@+128..255 post-loop)
#define OFF_H0S  OFF_MS
#define SMEM_FLOATS 12848
#define SMEM_BYTES  (SMEM_FLOATS*4)

typedef unsigned long long u64;

__device__ __forceinline__ float siluf(float v) { return v / (1.0f + __expf(-v)); }
__device__ __forceinline__ ulonglong2 ld128p(const float* p) { return *(const ulonglong2*)p; }
__device__ __forceinline__ void fma2(u64& d, u64 a, u64 b) {
    asm("fma.rn.f32x2 %0, %1, %2, %0;" : "+l"(d) : "l"(a), "l"(b));
}
__device__ __forceinline__ float hsum(u64 v) {
    float lo, hi; asm("mov.b64 {%0, %1}, %2;" : "=f"(lo), "=f"(hi) : "l"(v));
    return lo + hi;
}

// stage K2 k-pairs of a [2*K2 x 64] row-major matrix into paired layout
template<int K2>
__device__ __forceinline__ void stagePairs(float* dst, const float* src, int tid) {
    const float4* s4 = (const float4*)src;
    float4* d4 = (float4*)dst;
    for (int f = tid; f < K2 * 16; f += TPB) {
        int k2 = f >> 4, c4 = f & 15;
        float4 r0 = __ldg(&s4[(2*k2)*16 + c4]);
        float4 r1 = __ldg(&s4[(2*k2+1)*16 + c4]);
        d4[(k2*64 + c4*4) >> 1]       = make_float4(r0.x, r1.x, r0.y, r1.y);
        d4[((k2*64 + c4*4) >> 1) + 1] = make_float4(r0.z, r1.z, r0.w, r1.w);
    }
}

// plain row-major copy of a 64x64 matrix
__device__ __forceinline__ void stagePlain64(float* dst, const float* src, int tid) {
    float4* q = (float4*)dst;
    const float4* g = (const float4*)src;
    for (int i = tid; i < 1024; i += TPB) q[i] = __ldg(&g[i]);
}

extern "C" __global__ void __launch_bounds__(TPB, 4)
egnn_kernel(const float* __restrict__ h0,   const float* __restrict__ x0,
            const float* __restrict__ Wemb, const float* __restrict__ bemb,
            const float* __restrict__ We1,  const float* __restrict__ be1,
            const float* __restrict__ We2,  const float* __restrict__ be2,
            const float* __restrict__ Wx,   const float* __restrict__ bx,
            const float* __restrict__ Wh1,  const float* __restrict__ bh1,
            const float* __restrict__ Wh2,  const float* __restrict__ bh2,
            const float* __restrict__ w_act,const float* __restrict__ log_std,
            float* __restrict__ out)
{
    extern __shared__ float sm[];
    float* WA  = sm + OFF_WA;
    float* WB  = sm + OFF_WB;
    const u64* WA2 = (const u64*)WA;   // paired [k2*64 + c]
    const u64* WB2 = (const u64*)WB;   // paired view (Wemb / Wh2 phases)
    float* hs  = sm + OFF_H;
    float* P2p = sm + OFF_P2;
    float* xs0 = sm + OFF_XS0;
    float* xs1 = sm + OFF_XS1;
    float* rad = sm + OFF_RAD;
    float* h0s = sm + OFF_H0S;
    float* ms  = sm + OFF_MS;

    const int tid  = threadIdx.x;
    const int w    = tid >> 5;
    const int lane = tid & 31;
    const int env  = blockIdx.x;
    const int base = env * NAG;
    const int iA = 2 * w, iB = 2 * w + 1;
    float* msw = ms + w * 384;          // edge scratch; agg@+0..127, t1s@+128..255 post-loop

    // ---------- phase 0: stage x, h0, W_embed(paired) ; embed ----------
    if (tid < NAG * NAG) xs0[tid] = __ldg(&x0[base * 12 + tid]);
    for (int t = tid; t < NAG * 32; t += TPB) h0s[t] = __ldg(&h0[base * 32 + t]);
    stagePairs<16>(WB, Wemb, tid);
    __syncthreads();
    {   // h = h0 @ Wemb + bemb
        u64 a0A = 0ull, a1A = 0ull, a0B = 0ull, a1B = 0ull;
        #pragma unroll
        for (int k4 = 0; k4 < 8; k4++) {
            ulonglong2 hA = ld128p(&h0s[iA*32 + k4*4]);
            ulonglong2 hB = ld128p(&h0s[iB*32 + k4*4]);
            u64 w0a = WB2[(2*k4)*64 + lane],   w1a = WB2[(2*k4)*64 + lane + 32];
            u64 w0b = WB2[(2*k4+1)*64 + lane], w1b = WB2[(2*k4+1)*64 + lane + 32];
            fma2(a0A, w0a, hA.x); fma2(a1A, w1a, hA.x);
            fma2(a0A, w0b, hA.y); fma2(a1A, w1b, hA.y);
            fma2(a0B, w0a, hB.x); fma2(a1B, w1a, hB.x);
            fma2(a0B, w0b, hB.y); fma2(a1B, w1b, hB.y);
        }
        float b0 = __ldg(&bemb[lane]), b1 = __ldg(&bemb[lane + 32]);
        hs[iA*64 + lane]      = hsum(a0A) + b0;
        hs[iA*64 + lane + 32] = hsum(a1A) + b1;
        hs[iB*64 + lane]      = hsum(a0B) + b0;
        hs[iB*64 + lane + 32] = hsum(a1B) + b1;
    }

    // ---------- layers ----------
    for (int l = 0; l < 2; l++) {
        __syncthreads();                         // (1) WB free
        float* xsr = (l == 0) ? xs0 : xs1;
        float* xsw = (l == 0) ? xs1 : xs0;
        stagePairs<32>(WA, We1 + l * 8448, tid);        // We1 rows 0..63 (paired)
        stagePlain64(WB, We2 + l * 4096, tid);          // We2 plain row-major
        if (tid < 132) {   // radial per edge
            int e = tid, i = e / 11, tt = e - 11 * i, j = tt + (tt >= i);
            float s0 = 0.f, s1 = 0.f, s2 = 0.f, s3 = 0.f;
            #pragma unroll
            for (int d = 0; d < 3; d++) {
                float d0 = xsr[i*12 + d*4 + 0] - xsr[j*12 + d*4 + 0]; s0 += d0*d0;
                float d1 = xsr[i*12 + d*4 + 1] - xsr[j*12 + d*4 + 1]; s1 += d1*d1;
                float d2 = xsr[i*12 + d*4 + 2] - xsr[j*12 + d*4 + 2]; s2 += d2*d2;
                float d3 = xsr[i*12 + d*4 + 3] - xsr[j*12 + d*4 + 3]; s3 += d3*d3;
            }
            ((float4*)rad)[e] = make_float4(s0, s1, s2, s3);
        }
        __syncthreads();                         // (2)

        // ---- P1 pass: hi @ We1[0:64] + be1 (kept in regs) ----
        float PiA0, PiA1, PiB0, PiB1;
        {
            u64 a0A = 0ull, a1A = 0ull, a0B = 0ull, a1B = 0ull;
            #pragma unroll
            for (int k4 = 0; k4 < 16; k4++) {
                ulonglong2 hA = ld128p(&hs[iA*64 + k4*4]);
                ulonglong2 hB = ld128p(&hs[iB*64 + k4*4]);
                #pragma unroll
                for (int s = 0; s < 2; s++) {
                    int k2 = 2*k4 + s;
                    u64 hpA = s ? hA.y : hA.x;
                    u64 hpB = s ? hB.y : hB.x;
                    u64 w0 = WA2[k2*64 + lane], w1 = WA2[k2*64 + lane + 32];
                    fma2(a0A, w0, hpA); fma2(a1A, w1, hpA);
                    fma2(a0B, w0, hpB); fma2(a1B, w1, hpB);
                }
            }
            float b0 = __ldg(&be1[l*64 + lane]), b1 = __ldg(&be1[l*64 + lane + 32]);
            PiA0 = hsum(a0A) + b0; PiA1 = hsum(a1A) + b1;
            PiB0 = hsum(a0B) + b0; PiB1 = hsum(a1B) + b1;
        }
        __syncthreads();                         // (3) WA consumed
        stagePairs<32>(WA, We1 + l * 8448 + 4096, tid); // We1 rows 64..127
        __syncthreads();                         // (4)
        // ---- P2 pass: hj @ We1[64:128] -> smem ----
        {
            u64 a2A = 0ull, a3A = 0ull, a2B = 0ull, a3B = 0ull;
            #pragma unroll
            for (int k4 = 0; k4 < 16; k4++) {
                ulonglong2 hA = ld128p(&hs[iA*64 + k4*4]);
                ulonglong2 hB = ld128p(&hs[iB*64 + k4*4]);
                #pragma unroll
                for (int s = 0; s < 2; s++) {
                    int k2 = 2*k4 + s;
                    u64 hpA = s ? hA.y : hA.x;
                    u64 hpB = s ? hB.y : hB.x;
                    u64 w2 = WA2[k2*64 + lane], w3 = WA2[k2*64 + lane + 32];
                    fma2(a2A, w2, hpA); fma2(a3A, w3, hpA);
                    fma2(a2B, w2, hpB); fma2(a3B, w3, hpB);
                }
            }
            ((float2*)P2p)[iA*32 + lane] = make_float2(hsum(a2A), hsum(a3A));
            ((float2*)P2p)[iB*32 + lane] = make_float2(hsum(a2B), hsum(a3B));
        }
        __syncthreads();                         // (5) P2p visible to all

        // ---- edge phase: warp owns nodes iA, iB (22 edges, batch 6 scalar) ----
        {
            const float4 wxA = __ldg((const float4*)&Wx[l*256 + lane*4]);
            const float4 wxB = __ldg((const float4*)&Wx[l*256 + (lane+32)*4]);
            const float4 bxv = __ldg((const float4*)&bx[l*4]);
            const float be2a = __ldg(&be2[l*64 + lane]);
            const float be2b = __ldg(&be2[l*64 + lane + 32]);
            const float xiA = (lane < 12) ? xsr[iA*12 + lane] : 0.f;
            const float xiB = (lane < 12) ? xsr[iB*12 + lane] : 0.f;
            float agA0 = 0.f, agB0 = 0.f, agA1 = 0.f, agB1 = 0.f;
            float dx0 = 0.f, dx1 = 0.f;
            const bool lb0 = lane & 1, lb1 = lane & 2;

            #pragma unroll
            for (int g0 = 0; g0 < 22; g0 += 6) {
                const int cnt = (22 - g0 < 6) ? (22 - g0) : 6;
                // MLP1 (radial weights scoped per pass)
                {
                    float wrA[4], wrB[4];
                    #pragma unroll
                    for (int v = 0; v < 4; v++) {
                        wrA[v] = __ldg(&We1[l*8448 + (128+v)*64 + lane]);
                        wrB[v] = __ldg(&We1[l*8448 + (128+v)*64 + lane + 32]);
                    }
                    #pragma unroll
                    for (int gg = 0; gg < 6; gg++) if (gg < cnt) {
                        const int t = g0 + gg;
                        const int i  = (t < 11) ? iA : iB;
                        const int tt = (t < 11) ? t : (t - 11);
                        const int j  = tt + (tt >= i);
                        float2 pj = ((const float2*)P2p)[j*32 + lane];
                        float4 rv = ((const float4*)rad)[i*11 + tt];
                        float P1a = (t < 11) ? PiA0 : PiB0;
                        float P1b = (t < 11) ? PiA1 : PiB1;
                        float aA = P1a + pj.x
                                 + rv.x*wrA[0] + rv.y*wrA[1] + rv.z*wrA[2] + rv.w*wrA[3];
                        float aB = P1b + pj.y
                                 + rv.x*wrB[0] + rv.y*wrB[1] + rv.z*wrB[2] + rv.w*wrB[3];
                        msw[gg*64 + lane]      = siluf(aA);
                        msw[gg*64 + lane + 32] = siluf(aB);
                    }
                }
                __syncwarp();
                // MLP2: scalar FFMA, plain row-major We2, weights amortized over 6 edges
                float acc0[6], acc1[6];
                #pragma unroll
                for (int gg = 0; gg < 6; gg++) { acc0[gg] = be2a; acc1[gg] = be2b; }
                #pragma unroll
                for (int k4 = 0; k4 < 16; k4++) {
                    float w00 = WB[(4*k4+0)*64 + lane];
                    float w01 = WB[(4*k4+1)*64 + lane];
                    float w02 = WB[(4*k4+2)*64 + lane];
                    float w03 = WB[(4*k4+3)*64 + lane];
                    float w10 = WB[(4*k4+0)*64 + lane + 32];
                    float w11 = WB[(4*k4+1)*64 + lane + 32];
                    float w12 = WB[(4*k4+2)*64 + lane + 32];
                    float w13 = WB[(4*k4+3)*64 + lane + 32];
                    #pragma unroll
                    for (int gg = 0; gg < 6; gg++) if (gg < cnt) {
                        float4 aq = *(const float4*)&msw[gg*64 + k4*4];
                        acc0[gg] += aq.x*w00 + aq.y*w01 + aq.z*w02 + aq.w*w03;
                        acc1[gg] += aq.x*w10 + aq.y*w11 + aq.z*w12 + aq.w*w13;
                    }
                }
                // epilogue: 6-shuffle multi-value reduce
                #pragma unroll
                for (int gg = 0; gg < 6; gg++) if (gg < cnt) {
                    const int t = g0 + gg;
                    const int tt = (t < 11) ? t : (t - 11);
                    const int i  = (t < 11) ? iA : iB;
                    const int j  = tt + (tt >= i);
                    float m0  = siluf(acc0[gg]);
                    float m1v = siluf(acc1[gg]);
                    if (t < 11) { agA0 += m0; agB0 += m1v; }
                    else        { agA1 += m0; agB1 += m1v; }
                    float p0 = m0*wxA.x + m1v*wxB.x;
                    float p1 = m0*wxA.y + m1v*wxB.y;
                    float p2 = m0*wxA.z + m1v*wxB.z;
                    float p3 = m0*wxA.w + m1v*wxB.w;
                    float sA = __shfl_xor_sync(0xffffffffu, lb0 ? p0 : p1, 1);
                    float A  = (lb0 ? p1 : p0) + sA;
                    float sC = __shfl_xor_sync(0xffffffffu, lb0 ? p2 : p3, 1);
                    float C  = (lb0 ? p3 : p2) + sC;
                    float sR = __shfl_xor_sync(0xffffffffu, lb1 ? A : C, 2);
                    float R  = (lb1 ? C : A) + sR;
                    R += __shfl_xor_sync(0xffffffffu, R, 4);
                    R += __shfl_xor_sync(0xffffffffu, R, 8);
                    R += __shfl_xor_sync(0xffffffffu, R, 16);
                    if (lane < 12) {
                        int v = lane & 3;
                        float wc = R + ((v == 0) ? bxv.x : (v == 1) ? bxv.y :
                                        (v == 2) ? bxv.z : bxv.w);
                        float xi = (t < 11) ? xiA : xiB;
                        float d  = (xi - xsr[j*12 + lane]) * wc;
                        if (t < 11) dx0 += d; else dx1 += d;
                    }
                }
                __syncwarp();
            }
            // agg -> per-warp scratch (warp-private; msw fully consumed)
            msw[lane]           = agA0;
            msw[lane + 32]      = agB0;
            msw[64 + lane]      = agA1;
            msw[64 + lane + 32] = agB1;
            if (lane < 12) {
                xsw[iA*12 + lane] = xiA + dx0 * (1.0f / 11.0f);
                xsw[iB*12 + lane] = xiB + dx1 * (1.0f / 11.0f);
            }
        }
        __syncthreads();                         // (6) WA, WB free
        stagePairs<32>(WA, Wh1 + l * 8192, tid);        // Wh1 rows 0..63 (paired)
        stagePairs<32>(WB, Wh2 + l * 4096, tid);        // Wh2 paired
        __syncthreads();                         // (7)

        // t1 pass1: h @ Wh1[0:64] (accumulators persist across restage)
        u64 a0A = 0ull, a1A = 0ull, a0B = 0ull, a1B = 0ull;
        {
            #pragma unroll
            for (int k4 = 0; k4 < 16; k4++) {
                ulonglong2 hA = ld128p(&hs[iA*64 + k4*4]);
                ulonglong2 hB = ld128p(&hs[iB*64 + k4*4]);
                #pragma unroll
                for (int s = 0; s < 2; s++) {
                    int k2 = 2*k4 + s;
                    u64 hpA = s ? hA.y : hA.x;
                    u64 hpB = s ? hB.y : hB.x;
                    u64 w0 = WA2[k2*64 + lane], w1 = WA2[k2*64 + lane + 32];
                    fma2(a0A, w0, hpA); fma2(a1A, w1, hpA);
                    fma2(a0B, w0, hpB); fma2(a1B, w1, hpB);
                }
            }
        }
        __syncthreads();                         // (8) WA consumed
        stagePairs<32>(WA, Wh1 + l * 8192 + 4096, tid); // Wh1 rows 64..127
        __syncthreads();                         // (9)
        // t1 pass2: agg @ Wh1[64:128], silu -> t1s (per-warp scratch +128)
        {
            #pragma unroll
            for (int k4 = 0; k4 < 16; k4++) {
                ulonglong2 gA = ld128p(&msw[k4*4]);         // agg node iA
                ulonglong2 gB = ld128p(&msw[64 + k4*4]);    // agg node iB
                #pragma unroll
                for (int s = 0; s < 2; s++) {
                    int k2 = 2*k4 + s;
                    u64 gpA = s ? gA.y : gA.x;
                    u64 gpB = s ? gB.y : gB.x;
                    u64 w0 = WA2[k2*64 + lane], w1 = WA2[k2*64 + lane + 32];
                    fma2(a0A, w0, gpA); fma2(a1A, w1, gpA);
                    fma2(a0B, w0, gpB); fma2(a1B, w1, gpB);
                }
            }
            float b0 = __ldg(&bh1[l*64 + lane]), b1 = __ldg(&bh1[l*64 + lane + 32]);
            msw[128 + lane]      = siluf(hsum(a0A) + b0);
            msw[128 + lane + 32] = siluf(hsum(a1A) + b1);
            msw[192 + lane]      = siluf(hsum(a0B) + b0);
            msw[192 + lane + 32] = siluf(hsum(a1B) + b1);
        }
        __syncwarp();                             // t1s warp-private
        // h += t1 @ Wh2 + bh2  (paired WB)
        {
            u64 c0A = 0ull, c1A = 0ull, c0B = 0ull, c1B = 0ull;
            #pragma unroll
            for (int k4 = 0; k4 < 16; k4++) {
                ulonglong2 tA = ld128p(&msw[128 + k4*4]);
                ulonglong2 tB = ld128p(&msw[192 + k4*4]);
                #pragma unroll
                for (int s = 0; s < 2; s++) {
                    int k2 = 2*k4 + s;
                    u64 tpA = s ? tA.y : tA.x;
                    u64 tpB = s ? tB.y : tB.x;
                    u64 w0 = WB2[k2*64 + lane], w1 = WB2[k2*64 + lane + 32];
                    fma2(c0A, w0, tpA); fma2(c1A, w1, tpA);
                    fma2(c0B, w0, tpB); fma2(c1B, w1, tpB);
                }
            }
            float b0 = __ldg(&bh2[l*64 + lane]), b1 = __ldg(&bh2[l*64 + lane + 32]);
            hs[iA*64 + lane]      += hsum(c0A) + b0;
            hs[iA*64 + lane + 32] += hsum(c1A) + b1;
            hs[iB*64 + lane]      += hsum(c0B) + b0;
            hs[iB*64 + lane + 32] += hsum(c1B) + b1;
        }
    }
    __syncthreads();
    // ---------- output: mu = x . w_act (final x in xs0) ----------
    if (tid < NAG * 3) {
        int a = tid / 3, d = tid - 3 * a;
        float mu = 0.f;
        #pragma unroll
        for (int v = 0; v < 4; v++) mu += xs0[a*12 + d*4 + v] * __ldg(&w_act[v]);
        out[(base + a) * 3 + d] = mu;
        out[NNODE * 3 + (base + a) * 3 + d] =
            -__ldg(&log_std[d]) - 0.91893853320467274178f;
    }
}

extern "C" void kernel_launch(void* const* d_in, const int* in_sizes, int n_in,
                              void* d_out, int out_size)
{
    (void)in_sizes; (void)n_in; (void)out_size;
    cudaFuncSetAttribute(egnn_kernel,
                         cudaFuncAttributeMaxDynamicSharedMemorySize, SMEM_BYTES);
    egnn_kernel<<<NENV, TPB, SMEM_BYTES>>>(
        (const float*)d_in[0],  (const float*)d_in[1],
        (const float*)d_in[2],  (const float*)d_in[3],
        (const float*)d_in[4],  (const float*)d_in[5],
        (const float*)d_in[6],  (const float*)d_in[7],
        (const float*)d_in[8],  (const float*)d_in[9],
        (const float*)d_in[10], (const float*)d_in[11],
        (const float*)d_in[12], (const float*)d_in[13],
        (const float*)d_in[14], (const float*)d_in[15],
        (float*)d_out);
}

// round 14
// speedup vs baseline: 1.1504x; 1.1504x over previous
#include <cuda_runtime.h>

#define NAG    12
#define NENV   4096
#define NNODE  (NENV*NAG)
#define TPB    192

// shared float offsets
#define OFF_WA   0        // 4096 paired-k (half of We1 / Wh1)
#define OFF_WB   4096     // 4096 paired-k (Wemb / We2 / Wh2)
#define OFF_H    8192     // 12x64
#define OFF_P2   8960     // P2 float2[12][32]
#define OFF_XS0  9728     // 144
#define OFF_XS1  9872     // 144
#define OFF_RAD  10016    // 132x4
#define OFF_MS   10544    // 6 warps x 384 (msw batch6; agg@+0..127, t1s@+128..255 post-loop)
#define OFF_H0S  OFF_MS
#define SMEM_FLOATS 12848
#define SMEM_BYTES  (SMEM_FLOATS*4)

typedef unsigned long long u64;

__device__ __forceinline__ float siluf(float v) { return v / (1.0f + __expf(-v)); }
__device__ __forceinline__ ulonglong2 ld128p(const float* p) { return *(const ulonglong2*)p; }
__device__ __forceinline__ void fma2(u64& d, u64 a, u64 b) {
    asm("fma.rn.f32x2 %0, %1, %2, %0;" : "+l"(d) : "l"(a), "l"(b));
}
__device__ __forceinline__ float hsum(u64 v) {
    float lo, hi; asm("mov.b64 {%0, %1}, %2;" : "=f"(lo), "=f"(hi) : "l"(v));
    return lo + hi;
}

// stage K2 k-pairs of a [2*K2 x 64] row-major matrix into paired layout
template<int K2>
__device__ __forceinline__ void stagePairs(float* dst, const float* src, int tid) {
    const float4* s4 = (const float4*)src;
    float4* d4 = (float4*)dst;
    for (int f = tid; f < K2 * 16; f += TPB) {
        int k2 = f >> 4, c4 = f & 15;
        float4 r0 = __ldg(&s4[(2*k2)*16 + c4]);
        float4 r1 = __ldg(&s4[(2*k2+1)*16 + c4]);
        d4[(k2*64 + c4*4) >> 1]       = make_float4(r0.x, r1.x, r0.y, r1.y);
        d4[((k2*64 + c4*4) >> 1) + 1] = make_float4(r0.z, r1.z, r0.w, r1.w);
    }
}

extern "C" __global__ void __launch_bounds__(TPB, 4)
egnn_kernel(const float* __restrict__ h0,   const float* __restrict__ x0,
            const float* __restrict__ Wemb, const float* __restrict__ bemb,
            const float* __restrict__ We1,  const float* __restrict__ be1,
            const float* __restrict__ We2,  const float* __restrict__ be2,
            const float* __restrict__ Wx,   const float* __restrict__ bx,
            const float* __restrict__ Wh1,  const float* __restrict__ bh1,
            const float* __restrict__ Wh2,  const float* __restrict__ bh2,
            const float* __restrict__ w_act,const float* __restrict__ log_std,
            float* __restrict__ out)
{
    extern __shared__ float sm[];
    float* WA  = sm + OFF_WA;
    float* WB  = sm + OFF_WB;
    const u64* WA2 = (const u64*)WA;   // paired [k2*64 + c]
    const u64* WB2 = (const u64*)WB;
    float* hs  = sm + OFF_H;
    float* P2p = sm + OFF_P2;
    float* xs0 = sm + OFF_XS0;
    float* xs1 = sm + OFF_XS1;
    float* rad = sm + OFF_RAD;
    float* h0s = sm + OFF_H0S;
    float* ms  = sm + OFF_MS;

    const int tid  = threadIdx.x;
    const int w    = tid >> 5;
    const int lane = tid & 31;
    const int env  = blockIdx.x;
    const int base = env * NAG;
    const int iA = 2 * w, iB = 2 * w + 1;
    float* msw = ms + w * 384;          // edge scratch; agg@+0..127, t1s@+128..255 post-loop

    // ---------- phase 0: stage x, h0, W_embed(paired) ; embed ----------
    if (tid < NAG * NAG) xs0[tid] = __ldg(&x0[base * 12 + tid]);
    for (int t = tid; t < NAG * 32; t += TPB) h0s[t] = __ldg(&h0[base * 32 + t]);
    stagePairs<16>(WB, Wemb, tid);
    __syncthreads();
    {   // h = h0 @ Wemb + bemb
        u64 a0A = 0ull, a1A = 0ull, a0B = 0ull, a1B = 0ull;
        #pragma unroll
        for (int k4 = 0; k4 < 8; k4++) {
            ulonglong2 hA = ld128p(&h0s[iA*32 + k4*4]);
            ulonglong2 hB = ld128p(&h0s[iB*32 + k4*4]);
            u64 w0a = WB2[(2*k4)*64 + lane],   w1a = WB2[(2*k4)*64 + lane + 32];
            u64 w0b = WB2[(2*k4+1)*64 + lane], w1b = WB2[(2*k4+1)*64 + lane + 32];
            fma2(a0A, w0a, hA.x); fma2(a1A, w1a, hA.x);
            fma2(a0A, w0b, hA.y); fma2(a1A, w1b, hA.y);
            fma2(a0B, w0a, hB.x); fma2(a1B, w1a, hB.x);
            fma2(a0B, w0b, hB.y); fma2(a1B, w1b, hB.y);
        }
        float b0 = __ldg(&bemb[lane]), b1 = __ldg(&bemb[lane + 32]);
        hs[iA*64 + lane]      = hsum(a0A) + b0;
        hs[iA*64 + lane + 32] = hsum(a1A) + b1;
        hs[iB*64 + lane]      = hsum(a0B) + b0;
        hs[iB*64 + lane + 32] = hsum(a1B) + b1;
    }

    // ---------- layers ----------
    for (int l = 0; l < 2; l++) {
        __syncthreads();                         // (1) WB free
        float* xsr = (l == 0) ? xs0 : xs1;
        float* xsw = (l == 0) ? xs1 : xs0;
        stagePairs<32>(WA, We1 + l * 8448, tid);        // We1 rows 0..63
        stagePairs<32>(WB, We2 + l * 4096, tid);
        if (tid < 132) {   // radial per edge
            int e = tid, i = e / 11, tt = e - 11 * i, j = tt + (tt >= i);
            float s0 = 0.f, s1 = 0.f, s2 = 0.f, s3 = 0.f;
            #pragma unroll
            for (int d = 0; d < 3; d++) {
                float d0 = xsr[i*12 + d*4 + 0] - xsr[j*12 + d*4 + 0]; s0 += d0*d0;
                float d1 = xsr[i*12 + d*4 + 1] - xsr[j*12 + d*4 + 1]; s1 += d1*d1;
                float d2 = xsr[i*12 + d*4 + 2] - xsr[j*12 + d*4 + 2]; s2 += d2*d2;
                float d3 = xsr[i*12 + d*4 + 3] - xsr[j*12 + d*4 + 3]; s3 += d3*d3;
            }
            ((float4*)rad)[e] = make_float4(s0, s1, s2, s3);
        }
        __syncthreads();                         // (2)

        // ---- P1 pass: hi @ We1[0:64] + be1 (kept in regs) ----
        float PiA0, PiA1, PiB0, PiB1;
        {
            u64 a0A = 0ull, a1A = 0ull, a0B = 0ull, a1B = 0ull;
            #pragma unroll
            for (int k4 = 0; k4 < 16; k4++) {
                ulonglong2 hA = ld128p(&hs[iA*64 + k4*4]);
                ulonglong2 hB = ld128p(&hs[iB*64 + k4*4]);
                #pragma unroll
                for (int s = 0; s < 2; s++) {
                    int k2 = 2*k4 + s;
                    u64 hpA = s ? hA.y : hA.x;
                    u64 hpB = s ? hB.y : hB.x;
                    u64 w0 = WA2[k2*64 + lane], w1 = WA2[k2*64 + lane + 32];
                    fma2(a0A, w0, hpA); fma2(a1A, w1, hpA);
                    fma2(a0B, w0, hpB); fma2(a1B, w1, hpB);
                }
            }
            float b0 = __ldg(&be1[l*64 + lane]), b1 = __ldg(&be1[l*64 + lane + 32]);
            PiA0 = hsum(a0A) + b0; PiA1 = hsum(a1A) + b1;
            PiB0 = hsum(a0B) + b0; PiB1 = hsum(a1B) + b1;
        }
        __syncthreads();                         // (3) WA consumed
        stagePairs<32>(WA, We1 + l * 8448 + 4096, tid); // We1 rows 64..127
        __syncthreads();                         // (4)
        // ---- P2 pass: hj @ We1[64:128] -> smem ----
        {
            u64 a2A = 0ull, a3A = 0ull, a2B = 0ull, a3B = 0ull;
            #pragma unroll
            for (int k4 = 0; k4 < 16; k4++) {
                ulonglong2 hA = ld128p(&hs[iA*64 + k4*4]);
                ulonglong2 hB = ld128p(&hs[iB*64 + k4*4]);
                #pragma unroll
                for (int s = 0; s < 2; s++) {
                    int k2 = 2*k4 + s;
                    u64 hpA = s ? hA.y : hA.x;
                    u64 hpB = s ? hB.y : hB.x;
                    u64 w2 = WA2[k2*64 + lane], w3 = WA2[k2*64 + lane + 32];
                    fma2(a2A, w2, hpA); fma2(a3A, w3, hpA);
                    fma2(a2B, w2, hpB); fma2(a3B, w3, hpB);
                }
            }
            ((float2*)P2p)[iA*32 + lane] = make_float2(hsum(a2A), hsum(a3A));
            ((float2*)P2p)[iB*32 + lane] = make_float2(hsum(a2B), hsum(a3B));
        }
        __syncthreads();                         // (5) P2p visible to all

        // ---- edge phase: warp owns nodes iA, iB (22 edges, batch 6 FFMA2) ----
        {
            const float xiA = (lane < 12) ? xsr[iA*12 + lane] : 0.f;
            const float xiB = (lane < 12) ? xsr[iB*12 + lane] : 0.f;
            float agA0 = 0.f, agB0 = 0.f, agA1 = 0.f, agB1 = 0.f;
            float dx0 = 0.f, dx1 = 0.f;
            const bool lb0 = lane & 1, lb1 = lane & 2;

            #pragma unroll
            for (int g0 = 0; g0 < 22; g0 += 6) {
                const int cnt = (22 - g0 < 6) ? (22 - g0) : 6;
                // MLP1 (radial weights scoped per pass)
                {
                    float wrA[4], wrB[4];
                    #pragma unroll
                    for (int v = 0; v < 4; v++) {
                        wrA[v] = __ldg(&We1[l*8448 + (128+v)*64 + lane]);
                        wrB[v] = __ldg(&We1[l*8448 + (128+v)*64 + lane + 32]);
                    }
                    #pragma unroll
                    for (int gg = 0; gg < 6; gg++) if (gg < cnt) {
                        const int t = g0 + gg;
                        const int i  = (t < 11) ? iA : iB;
                        const int tt = (t < 11) ? t : (t - 11);
                        const int j  = tt + (tt >= i);
                        float2 pj = ((const float2*)P2p)[j*32 + lane];
                        float4 rv = ((const float4*)rad)[i*11 + tt];
                        float P1a = (t < 11) ? PiA0 : PiB0;
                        float P1b = (t < 11) ? PiA1 : PiB1;
                        float aA = P1a + pj.x
                                 + rv.x*wrA[0] + rv.y*wrA[1] + rv.z*wrA[2] + rv.w*wrA[3];
                        float aB = P1b + pj.y
                                 + rv.x*wrB[0] + rv.y*wrB[1] + rv.z*wrB[2] + rv.w*wrB[3];
                        msw[gg*64 + lane]      = siluf(aA);
                        msw[gg*64 + lane + 32] = siluf(aB);
                    }
                }
                __syncwarp();
                // MLP2: FFMA2, weights amortized over up to 6 edges
                u64 acc0[6], acc1[6];
                #pragma unroll
                for (int gg = 0; gg < 6; gg++) { acc0[gg] = 0ull; acc1[gg] = 0ull; }
                #pragma unroll
                for (int k4 = 0; k4 < 16; k4++) {
                    u64 w00 = WB2[(2*k4)*64 + lane];
                    u64 w01 = WB2[(2*k4+1)*64 + lane];
                    u64 w10 = WB2[(2*k4)*64 + lane + 32];
                    u64 w11 = WB2[(2*k4+1)*64 + lane + 32];
                    #pragma unroll
                    for (int gg = 0; gg < 6; gg++) if (gg < cnt) {
                        ulonglong2 aq = ld128p(&msw[gg*64 + k4*4]);
                        fma2(acc0[gg], w00, aq.x); fma2(acc0[gg], w01, aq.y);
                        fma2(acc1[gg], w10, aq.x); fma2(acc1[gg], w11, aq.y);
                    }
                }
                // epilogue: constants reloaded per pass (keeps MLP2 liveness low)
                {
                    const float4 wxA = __ldg((const float4*)&Wx[l*256 + lane*4]);
                    const float4 wxB = __ldg((const float4*)&Wx[l*256 + (lane+32)*4]);
                    const float4 bxv = __ldg((const float4*)&bx[l*4]);
                    const float be2a = __ldg(&be2[l*64 + lane]);
                    const float be2b = __ldg(&be2[l*64 + lane + 32]);
                    #pragma unroll
                    for (int gg = 0; gg < 6; gg++) if (gg < cnt) {
                        const int t = g0 + gg;
                        const int tt = (t < 11) ? t : (t - 11);
                        const int i  = (t < 11) ? iA : iB;
                        const int j  = tt + (tt >= i);
                        float m0  = siluf(hsum(acc0[gg]) + be2a);
                        float m1v = siluf(hsum(acc1[gg]) + be2b);
                        if (t < 11) { agA0 += m0; agB0 += m1v; }
                        else        { agA1 += m0; agB1 += m1v; }
                        float p0 = m0*wxA.x + m1v*wxB.x;
                        float p1 = m0*wxA.y + m1v*wxB.y;
                        float p2 = m0*wxA.z + m1v*wxB.z;
                        float p3 = m0*wxA.w + m1v*wxB.w;
                        float sA = __shfl_xor_sync(0xffffffffu, lb0 ? p0 : p1, 1);
                        float A  = (lb0 ? p1 : p0) + sA;
                        float sC = __shfl_xor_sync(0xffffffffu, lb0 ? p2 : p3, 1);
                        float C  = (lb0 ? p3 : p2) + sC;
                        float sR = __shfl_xor_sync(0xffffffffu, lb1 ? A : C, 2);
                        float R  = (lb1 ? C : A) + sR;
                        R += __shfl_xor_sync(0xffffffffu, R, 4);
                        R += __shfl_xor_sync(0xffffffffu, R, 8);
                        R += __shfl_xor_sync(0xffffffffu, R, 16);
                        if (lane < 12) {
                            int v = lane & 3;
                            float wc = R + ((v == 0) ? bxv.x : (v == 1) ? bxv.y :
                                            (v == 2) ? bxv.z : bxv.w);
                            float xi = (t < 11) ? xiA : xiB;
                            float d  = (xi - xsr[j*12 + lane]) * wc;
                            if (t < 11) dx0 += d; else dx1 += d;
                        }
                    }
                }
                __syncwarp();
            }
            // agg -> per-warp scratch (warp-private; msw fully consumed)
            msw[lane]           = agA0;
            msw[lane + 32]      = agB0;
            msw[64 + lane]      = agA1;
            msw[64 + lane + 32] = agB1;
            if (lane < 12) {
                xsw[iA*12 + lane] = xiA + dx0 * (1.0f / 11.0f);
                xsw[iB*12 + lane] = xiB + dx1 * (1.0f / 11.0f);
            }
        }
        __syncthreads();                         // (6) WA, WB free
        stagePairs<32>(WA, Wh1 + l * 8192, tid);        // Wh1 rows 0..63
        stagePairs<32>(WB, Wh2 + l * 4096, tid);
        __syncthreads();                         // (7)

        // t1 pass1: h @ Wh1[0:64] (accumulators persist across restage)
        u64 a0A = 0ull, a1A = 0ull, a0B = 0ull, a1B = 0ull;
        {
            #pragma unroll
            for (int k4 = 0; k4 < 16; k4++) {
                ulonglong2 hA = ld128p(&hs[iA*64 + k4*4]);
                ulonglong2 hB = ld128p(&hs[iB*64 + k4*4]);
                #pragma unroll
                for (int s = 0; s < 2; s++) {
                    int k2 = 2*k4 + s;
                    u64 hpA = s ? hA.y : hA.x;
                    u64 hpB = s ? hB.y : hB.x;
                    u64 w0 = WA2[k2*64 + lane], w1 = WA2[k2*64 + lane + 32];
                    fma2(a0A, w0, hpA); fma2(a1A, w1, hpA);
                    fma2(a0B, w0, hpB); fma2(a1B, w1, hpB);
                }
            }
        }
        __syncthreads();                         // (8) WA consumed
        stagePairs<32>(WA, Wh1 + l * 8192 + 4096, tid); // Wh1 rows 64..127
        __syncthreads();                         // (9)
        // t1 pass2: agg @ Wh1[64:128], silu -> t1s (per-warp scratch +128)
        {
            #pragma unroll
            for (int k4 = 0; k4 < 16; k4++) {
                ulonglong2 gA = ld128p(&msw[k4*4]);         // agg node iA
                ulonglong2 gB = ld128p(&msw[64 + k4*4]);    // agg node iB
                #pragma unroll
                for (int s = 0; s < 2; s++) {
                    int k2 = 2*k4 + s;
                    u64 gpA = s ? gA.y : gA.x;
                    u64 gpB = s ? gB.y : gB.x;
                    u64 w0 = WA2[k2*64 + lane], w1 = WA2[k2*64 + lane + 32];
                    fma2(a0A, w0, gpA); fma2(a1A, w1, gpA);
                    fma2(a0B, w0, gpB); fma2(a1B, w1, gpB);
                }
            }
            float b0 = __ldg(&bh1[l*64 + lane]), b1 = __ldg(&bh1[l*64 + lane + 32]);
            msw[128 + lane]      = siluf(hsum(a0A) + b0);
            msw[128 + lane + 32] = siluf(hsum(a1A) + b1);
            msw[192 + lane]      = siluf(hsum(a0B) + b0);
            msw[192 + lane + 32] = siluf(hsum(a1B) + b1);
        }
        __syncwarp();                             // t1s warp-private
        // h += t1 @ Wh2 + bh2  (paired WB)
        {
            u64 c0A = 0ull, c1A = 0ull, c0B = 0ull, c1B = 0ull;
            #pragma unroll
            for (int k4 = 0; k4 < 16; k4++) {
                ulonglong2 tA = ld128p(&msw[128 + k4*4]);
                ulonglong2 tB = ld128p(&msw[192 + k4*4]);
                #pragma unroll
                for (int s = 0; s < 2; s++) {
                    int k2 = 2*k4 + s;
                    u64 tpA = s ? tA.y : tA.x;
                    u64 tpB = s ? tB.y : tB.x;
                    u64 w0 = WB2[k2*64 + lane], w1 = WB2[k2*64 + lane + 32];
                    fma2(c0A, w0, tpA); fma2(c1A, w1, tpA);
                    fma2(c0B, w0, tpB); fma2(c1B, w1, tpB);
                }
            }
            float b0 = __ldg(&bh2[l*64 + lane]), b1 = __ldg(&bh2[l*64 + lane + 32]);
            hs[iA*64 + lane]      += hsum(c0A) + b0;
            hs[iA*64 + lane + 32] += hsum(c1A) + b1;
            hs[iB*64 + lane]      += hsum(c0B) + b0;
            hs[iB*64 + lane + 32] += hsum(c1B) + b1;
        }
    }
    __syncthreads();
    // ---------- output: mu = x . w_act (final x in xs0) ----------
    if (tid < NAG * 3) {
        int a = tid / 3, d = tid - 3 * a;
        float mu = 0.f;
        #pragma unroll
        for (int v = 0; v < 4; v++) mu += xs0[a*12 + d*4 + v] * __ldg(&w_act[v]);
        out[(base + a) * 3 + d] = mu;
        out[NNODE * 3 + (base + a) * 3 + d] =
            -__ldg(&log_std[d]) - 0.91893853320467274178f;
    }
}

extern "C" void kernel_launch(void* const* d_in, const int* in_sizes, int n_in,
                              void* d_out, int out_size)
{
    (void)in_sizes; (void)n_in; (void)out_size;
    cudaFuncSetAttribute(egnn_kernel,
                         cudaFuncAttributeMaxDynamicSharedMemorySize, SMEM_BYTES);
    egnn_kernel<<<NENV, TPB, SMEM_BYTES>>>(
        (const float*)d_in[0],  (const float*)d_in[1],
        (const float*)d_in[2],  (const float*)d_in[3],
        (const float*)d_in[4],  (const float*)d_in[5],
        (const float*)d_in[6],  (const float*)d_in[7],
        (const float*)d_in[8],  (const float*)d_in[9],
        (const float*)d_in[10], (const float*)d_in[11],
        (const float*)d_in[12], (const float*)d_in[13],
        (const float*)d_in[14], (const float*)d_in[15],
        (float*)d_out);
}